// round 3
// baseline (speedup 1.0000x reference)
#include <cuda_runtime.h>
#include <math.h>

#define B_  2
#define S_  2048
#define D_  1024
#define H_  16
#define HD_ 64
#define M_  (B_*S_)      // 4096
#define NQKV 3072
#define KD  1024

// Scratch (static device globals — allocation-free per harness rules)
__device__ float g_qkv[M_ * NQKV];          // [B*S, 3*D]
__device__ float g_q[B_*H_*S_*HD_];         // [B,H,S,Hd]
__device__ float g_k[B_*H_*S_*HD_];
__device__ float g_v[B_*H_*S_*HD_];
__device__ float g_attn[M_ * D_];           // [B,S,D]

// ---------------------------------------------------------------------------
// Generic SGEMM: C[M,N] = A[M,K] @ W[N,K]^T + bias[N]
// BM=BN=128, BK=16, 256 threads, 8x8 per thread, transposed smem staging.
// ---------------------------------------------------------------------------
__global__ __launch_bounds__(256) void sgemm_bias_kernel(
    const float* __restrict__ A, const float* __restrict__ W,
    const float* __restrict__ bias, float* __restrict__ C,
    int M, int N, int K)
{
    const int LD = 132;                // padded stride (16B-aligned: 132*4=528)
    __shared__ float sA[16 * LD];
    __shared__ float sB[16 * LD];

    int tid = threadIdx.x;
    int tx = tid & 15, ty = tid >> 4;
    int rowBase = blockIdx.y * 128;
    int colBase = blockIdx.x * 128;

    float acc[8][8];
#pragma unroll
    for (int i = 0; i < 8; i++)
#pragma unroll
        for (int j = 0; j < 8; j++) acc[i][j] = 0.f;

    for (int kt = 0; kt < K; kt += 16) {
#pragma unroll
        for (int p = 0; p < 2; p++) {
            int slot = p * 256 + tid;      // 512 float4 slots
            int r  = slot >> 2;            // 0..127
            int kq = slot & 3;             // 0..3
            float4 fa = *(const float4*)(A + (size_t)(rowBase + r) * K + kt + kq * 4);
            sA[(kq*4+0)*LD + r] = fa.x;
            sA[(kq*4+1)*LD + r] = fa.y;
            sA[(kq*4+2)*LD + r] = fa.z;
            sA[(kq*4+3)*LD + r] = fa.w;
            float4 fb = *(const float4*)(W + (size_t)(colBase + r) * K + kt + kq * 4);
            sB[(kq*4+0)*LD + r] = fb.x;
            sB[(kq*4+1)*LD + r] = fb.y;
            sB[(kq*4+2)*LD + r] = fb.z;
            sB[(kq*4+3)*LD + r] = fb.w;
        }
        __syncthreads();
#pragma unroll
        for (int k = 0; k < 16; k++) {
            float af[8], bf[8];
            *(float4*)&af[0] = *(const float4*)&sA[k*LD + ty*8];
            *(float4*)&af[4] = *(const float4*)&sA[k*LD + ty*8 + 4];
            *(float4*)&bf[0] = *(const float4*)&sB[k*LD + tx*8];
            *(float4*)&bf[4] = *(const float4*)&sB[k*LD + tx*8 + 4];
#pragma unroll
            for (int i = 0; i < 8; i++)
#pragma unroll
                for (int j = 0; j < 8; j++)
                    acc[i][j] = fmaf(af[i], bf[j], acc[i][j]);
        }
        __syncthreads();
    }

#pragma unroll
    for (int i = 0; i < 8; i++) {
        int row = rowBase + ty * 8 + i;
#pragma unroll
        for (int j4 = 0; j4 < 8; j4 += 4) {
            int col = colBase + tx * 8 + j4;
            float4 bb = *(const float4*)(bias + col);
            float4 o;
            o.x = acc[i][j4+0] + bb.x;
            o.y = acc[i][j4+1] + bb.y;
            o.z = acc[i][j4+2] + bb.z;
            o.w = acc[i][j4+3] + bb.w;
            *(float4*)(C + (size_t)row * N + col) = o;
        }
    }
}

// ---------------------------------------------------------------------------
// RoPE + scatter: g_qkv [B,S,3,H,Hd] -> g_q/g_k (roped), g_v, layout [B,H,S,Hd]
// One thread per (which,b,h,s,pair i<32).
// ---------------------------------------------------------------------------
__global__ __launch_bounds__(256) void rope_scatter_kernel(
    const float* __restrict__ qkv,
    float* __restrict__ q, float* __restrict__ k, float* __restrict__ v)
{
    int idx = blockIdx.x * blockDim.x + threadIdx.x;
    const int TOT = 3 * B_ * H_ * S_ * 32;
    if (idx >= TOT) return;
    int i = idx & 31;  int t = idx >> 5;
    int s = t & (S_ - 1); t >>= 11;
    int h = t & (H_ - 1); t >>= 4;
    int b = t & 1;
    int which = t >> 1;

    const float* src = qkv + (size_t)(b * S_ + s) * NQKV + which * D_ + h * HD_;
    float x1 = src[i];
    float x2 = src[i + 32];
    float* dst = (which == 0 ? q : which == 1 ? k : v)
               + (size_t)((b * H_ + h) * S_ + s) * HD_;
    if (which == 2) {
        dst[i]      = x1;
        dst[i + 32] = x2;
    } else {
        float inv = powf(10000.0f, -(float)i * (1.0f / 32.0f));
        float ang = (float)s * inv;
        float sn, c;
        sincosf(ang, &sn, &c);
        dst[i]      = x1 * c - x2 * sn;
        dst[i + 32] = x1 * sn + x2 * c;
    }
}

// ---------------------------------------------------------------------------
// Causal flash attention, fp32 SIMT. BM=BN=64, Hd=64, 256 threads (16x16, 4x4).
// Q/K staged d-major (transposed) for float4 fragment loads; S/P stored
// transposed [c][r] so the PV GEMM reads float4 row fragments.
// ---------------------------------------------------------------------------
__global__ __launch_bounds__(256) void flash_attn_kernel(
    const float* __restrict__ Q, const float* __restrict__ K,
    const float* __restrict__ V, float* __restrict__ Oattn)
{
    extern __shared__ float sm[];
    const int LD = 68;                       // padded, 16B-aligned stride
    float* sQt   = sm;                       // [64][68]  sQt[d*LD + r]
    float* sKt   = sQt + 64 * LD;            // [64][68]  sKt[d*LD + c]
    float* sV    = sKt + 64 * LD;            // [64][68]  sV[c*LD + hd]
    float* sP    = sV  + 64 * LD;            // [64][68]  sP[c*LD + r]
    float* sCorr = sP  + 64 * LD;            // [64]
    float* sLinv = sCorr + 64;               // [64]

    int tid = threadIdx.x;
    int tx = tid & 15, ty = tid >> 4;
    int qt = blockIdx.x;
    int bh = blockIdx.y;

    const float* Qb = Q + (size_t)bh * S_ * HD_;
    const float* Kb = K + (size_t)bh * S_ * HD_;
    const float* Vb = V + (size_t)bh * S_ * HD_;

    // Stage Q tile transposed
#pragma unroll
    for (int p = 0; p < 4; p++) {
        int slot = p * 256 + tid;            // 1024 float4 slots
        int r  = slot >> 4;                  // 0..63
        int q4 = slot & 15;                  // 0..15
        float4 f = *(const float4*)(Qb + (size_t)(qt * 64 + r) * HD_ + q4 * 4);
        sQt[(q4*4+0)*LD + r] = f.x;
        sQt[(q4*4+1)*LD + r] = f.y;
        sQt[(q4*4+2)*LD + r] = f.z;
        sQt[(q4*4+3)*LD + r] = f.w;
    }

    float o[4][4];
#pragma unroll
    for (int i = 0; i < 4; i++)
#pragma unroll
        for (int j = 0; j < 4; j++) o[i][j] = 0.f;
    float m_i = -1e30f, l_i = 0.f;

    for (int jt = 0; jt <= qt; jt++) {
        __syncthreads();   // prev PV GEMM done before restaging K/V
#pragma unroll
        for (int p = 0; p < 4; p++) {
            int slot = p * 256 + tid;
            int r  = slot >> 4;
            int q4 = slot & 15;
            float4 f = *(const float4*)(Kb + (size_t)(jt * 64 + r) * HD_ + q4 * 4);
            sKt[(q4*4+0)*LD + r] = f.x;
            sKt[(q4*4+1)*LD + r] = f.y;
            sKt[(q4*4+2)*LD + r] = f.z;
            sKt[(q4*4+3)*LD + r] = f.w;
            float4 g = *(const float4*)(Vb + (size_t)(jt * 64 + r) * HD_ + q4 * 4);
            *(float4*)&sV[r * LD + q4 * 4] = g;
        }
        __syncthreads();

        // S = Q K^T  (4x4 per thread over d)
        float s[4][4];
#pragma unroll
        for (int i = 0; i < 4; i++)
#pragma unroll
            for (int j = 0; j < 4; j++) s[i][j] = 0.f;
#pragma unroll 16
        for (int d = 0; d < 64; d++) {
            float4 a = *(const float4*)&sQt[d * LD + ty * 4];
            float4 b = *(const float4*)&sKt[d * LD + tx * 4];
            float af[4] = {a.x, a.y, a.z, a.w};
            float bf[4] = {b.x, b.y, b.z, b.w};
#pragma unroll
            for (int i = 0; i < 4; i++)
#pragma unroll
                for (int j = 0; j < 4; j++)
                    s[i][j] = fmaf(af[i], bf[j], s[i][j]);
        }
        // masked + scaled, store transposed
#pragma unroll
        for (int i = 0; i < 4; i++) {
            int rq = ty * 4 + i;
            int qpos = qt * 64 + rq;
#pragma unroll
            for (int j = 0; j < 4; j++) {
                int ck = tx * 4 + j;
                int kpos = jt * 64 + ck;
                float val = (kpos <= qpos) ? s[i][j] * 0.125f : -1e30f;
                sP[ck * LD + rq] = val;
            }
        }
        __syncthreads();

        // Online softmax: one thread per row (tid < 64)
        if (tid < 64) {
            float rmax = -1e30f;
#pragma unroll 8
            for (int c = 0; c < 64; c++)
                rmax = fmaxf(rmax, sP[c * LD + tid]);
            float newm = fmaxf(m_i, rmax);
            float corr = expf(m_i - newm);
            float sum = 0.f;
#pragma unroll 8
            for (int c = 0; c < 64; c++) {
                float pv = expf(sP[c * LD + tid] - newm);
                sP[c * LD + tid] = pv;
                sum += pv;
            }
            l_i = l_i * corr + sum;
            m_i = newm;
            sCorr[tid] = corr;
        }
        __syncthreads();

        // O = O*corr + P V
        float cr[4];
#pragma unroll
        for (int i = 0; i < 4; i++) {
            cr[i] = sCorr[ty * 4 + i];
#pragma unroll
            for (int j = 0; j < 4; j++) o[i][j] *= cr[i];
        }
#pragma unroll 16
        for (int c = 0; c < 64; c++) {
            float4 a = *(const float4*)&sP[c * LD + ty * 4];
            float4 b = *(const float4*)&sV[c * LD + tx * 4];
            float af[4] = {a.x, a.y, a.z, a.w};
            float bf[4] = {b.x, b.y, b.z, b.w};
#pragma unroll
            for (int i = 0; i < 4; i++)
#pragma unroll
                for (int j = 0; j < 4; j++)
                    o[i][j] = fmaf(af[i], bf[j], o[i][j]);
        }
    }

    if (tid < 64) sLinv[tid] = 1.0f / l_i;
    __syncthreads();

    int b = bh >> 4, h = bh & 15;
#pragma unroll
    for (int i = 0; i < 4; i++) {
        int srow = qt * 64 + ty * 4 + i;
        float inv = sLinv[ty * 4 + i];
        float4 ov;
        ov.x = o[i][0] * inv;
        ov.y = o[i][1] * inv;
        ov.z = o[i][2] * inv;
        ov.w = o[i][3] * inv;
        *(float4*)(Oattn + (size_t)(b * S_ + srow) * D_ + h * HD_ + tx * 4) = ov;
    }
}

// ---------------------------------------------------------------------------
extern "C" void kernel_launch(void* const* d_in, const int* in_sizes, int n_in,
                              void* d_out, int out_size)
{
    const float* x     = (const float*)d_in[0];
    const float* qkv_w = (const float*)d_in[1];
    const float* qkv_b = (const float*)d_in[2];
    const float* out_w = (const float*)d_in[3];
    const float* out_b = (const float*)d_in[4];
    float* out = (float*)d_out;

    float *qkv, *q, *k, *v, *attn;
    cudaGetSymbolAddress((void**)&qkv,  g_qkv);
    cudaGetSymbolAddress((void**)&q,    g_q);
    cudaGetSymbolAddress((void**)&k,    g_k);
    cudaGetSymbolAddress((void**)&v,    g_v);
    cudaGetSymbolAddress((void**)&attn, g_attn);

    // 1) QKV projection: [4096,1024] @ [3072,1024]^T + bias
    sgemm_bias_kernel<<<dim3(NQKV / 128, M_ / 128), 256>>>(
        x, qkv_w, qkv_b, qkv, M_, NQKV, KD);

    // 2) RoPE + scatter to [B,H,S,Hd]
    {
        const int TOT = 3 * B_ * H_ * S_ * 32;
        rope_scatter_kernel<<<(TOT + 255) / 256, 256>>>(qkv, q, k, v);
    }

    // 3) Causal flash attention
    {
        int smem = (4 * 64 * 68 + 128) * sizeof(float);   // 70144 B
        cudaFuncSetAttribute(flash_attn_kernel,
                             cudaFuncAttributeMaxDynamicSharedMemorySize, smem);
        flash_attn_kernel<<<dim3(S_ / 64, B_ * H_), 256, smem>>>(q, k, v, attn);
    }

    // 4) Output projection: [4096,1024] @ [1024,1024]^T + bias
    sgemm_bias_kernel<<<dim3(D_ / 128, M_ / 128), 256>>>(
        attn, out_w, out_b, out, M_, D_, KD);
}

// round 16
// speedup vs baseline: 1.2463x; 1.2463x over previous
#include <cuda_runtime.h>
#include <math.h>

#define B_  2
#define S_  2048
#define D_  1024
#define H_  16
#define HD_ 64
#define M_  (B_*S_)      // 4096
#define NQKV 3072
#define KD  1024

// Scratch (static device globals — allocation-free per harness rules)
__device__ float g_qkv[M_ * NQKV];          // [B*S, 3*D]
__device__ float g_q[B_*H_*S_*HD_];         // [B,H,S,Hd]
__device__ float g_k[B_*H_*S_*HD_];
__device__ float g_v[B_*H_*S_*HD_];
__device__ float g_attn[M_ * D_];           // [B,S,D]

// ---------------------------------------------------------------------------
// tf32 helpers
// ---------------------------------------------------------------------------
__device__ __forceinline__ float tf32_rna(float x) {
    float r;
    asm("cvt.rna.tf32.f32 %0, %1;" : "=f"(r) : "f"(x));
    return r;
}

// D += A(m16k8,row) * B(k8n8,col) ; all tf32 operands as b32 regs
__device__ __forceinline__ void mma8(float* d, const unsigned* a,
                                     unsigned b0, unsigned b1) {
    asm volatile(
        "mma.sync.aligned.m16n8k8.row.col.f32.tf32.tf32.f32 "
        "{%0,%1,%2,%3},{%4,%5,%6,%7},{%8,%9},{%0,%1,%2,%3};"
        : "+f"(d[0]), "+f"(d[1]), "+f"(d[2]), "+f"(d[3])
        : "r"(a[0]), "r"(a[1]), "r"(a[2]), "r"(a[3]), "r"(b0), "r"(b1));
}

// ---------------------------------------------------------------------------
// Tensor-core GEMM (3xTF32): C[M,N] = A[M,K] @ W[N,K]^T + bias[N]
// BM=BN=128, BK=32, 256 threads (8 warps, 2x4 -> 64x32 warp tiles).
// ---------------------------------------------------------------------------
#define LDsa 36   // 32 + 4 pad; lane bank = 4g+t, conflict-free

__global__ __launch_bounds__(256) void tf32_gemm_bias_kernel(
    const float* __restrict__ A, const float* __restrict__ W,
    const float* __restrict__ bias, float* __restrict__ C,
    int M, int N, int K)
{
    __shared__ float sA[128 * LDsa];
    __shared__ float sW[128 * LDsa];

    const int tid  = threadIdx.x;
    const int lane = tid & 31;
    const int wid  = tid >> 5;
    const int g = lane >> 2, t = lane & 3;
    const int rowBase = blockIdx.y * 128;
    const int colBase = blockIdx.x * 128;
    const int warpM = (wid >> 2) * 64;   // 0 / 64
    const int warpN = (wid & 3) * 32;    // 0 / 32 / 64 / 96

    float acc[4][4][4];
#pragma unroll
    for (int mf = 0; mf < 4; mf++)
#pragma unroll
        for (int nf = 0; nf < 4; nf++)
#pragma unroll
            for (int s = 0; s < 4; s++) acc[mf][nf][s] = 0.f;

    for (int kt = 0; kt < K; kt += 32) {
        __syncthreads();
#pragma unroll
        for (int p = 0; p < 4; p++) {
            int slot = p * 256 + tid;          // 1024 float4 slots
            int r = slot >> 3, c4 = slot & 7;
            *(float4*)&sA[r * LDsa + c4 * 4] =
                *(const float4*)(A + (size_t)(rowBase + r) * K + kt + c4 * 4);
            *(float4*)&sW[r * LDsa + c4 * 4] =
                *(const float4*)(W + (size_t)(colBase + r) * K + kt + c4 * 4);
        }
        __syncthreads();

#pragma unroll
        for (int kf = 0; kf < 4; kf++) {
            unsigned ah[4][4], al[4][4];
#pragma unroll
            for (int mf = 0; mf < 4; mf++) {
#pragma unroll
                for (int ss = 0; ss < 4; ss++) {
                    int r = warpM + mf * 16 + g + ((ss & 1) ? 8 : 0);
                    int c = kf * 8 + t + ((ss & 2) ? 4 : 0);
                    float v  = sA[r * LDsa + c];
                    float hi = tf32_rna(v);
                    ah[mf][ss] = __float_as_uint(hi);
                    al[mf][ss] = __float_as_uint(v - hi);
                }
            }
#pragma unroll
            for (int nf = 0; nf < 4; nf++) {
                float b0f = sW[(warpN + nf * 8 + g) * LDsa + kf * 8 + t];
                float b1f = sW[(warpN + nf * 8 + g) * LDsa + kf * 8 + t + 4];
                float b0h = tf32_rna(b0f), b1h = tf32_rna(b1f);
                unsigned ub0h = __float_as_uint(b0h), ub1h = __float_as_uint(b1h);
                unsigned ub0l = __float_as_uint(b0f - b0h);
                unsigned ub1l = __float_as_uint(b1f - b1h);
#pragma unroll
                for (int mf = 0; mf < 4; mf++) {
                    mma8(acc[mf][nf], ah[mf], ub0h, ub1h);
                    mma8(acc[mf][nf], ah[mf], ub0l, ub1l);
                    mma8(acc[mf][nf], al[mf], ub0h, ub1h);
                }
            }
        }
    }

    // epilogue: c0=C[g][2t], c1=C[g][2t+1], c2=C[g+8][2t], c3=C[g+8][2t+1]
#pragma unroll
    for (int mf = 0; mf < 4; mf++) {
#pragma unroll
        for (int nf = 0; nf < 4; nf++) {
            int r0 = rowBase + warpM + mf * 16 + g;
            int c0 = colBase + warpN + nf * 8 + 2 * t;
            float b0 = bias[c0], b1 = bias[c0 + 1];
            *(float2*)&C[(size_t)r0 * N + c0] =
                make_float2(acc[mf][nf][0] + b0, acc[mf][nf][1] + b1);
            *(float2*)&C[(size_t)(r0 + 8) * N + c0] =
                make_float2(acc[mf][nf][2] + b0, acc[mf][nf][3] + b1);
        }
    }
}

// ---------------------------------------------------------------------------
// RoPE + scatter: g_qkv [B,S,3,H,Hd] -> g_q/g_k (roped), g_v, layout [B,H,S,Hd]
// ---------------------------------------------------------------------------
__global__ __launch_bounds__(256) void rope_scatter_kernel(
    const float* __restrict__ qkv,
    float* __restrict__ q, float* __restrict__ k, float* __restrict__ v)
{
    int idx = blockIdx.x * blockDim.x + threadIdx.x;
    const int TOT = 3 * B_ * H_ * S_ * 32;
    if (idx >= TOT) return;
    int i = idx & 31;  int t = idx >> 5;
    int s = t & (S_ - 1); t >>= 11;
    int h = t & (H_ - 1); t >>= 4;
    int b = t & 1;
    int which = t >> 1;

    const float* src = qkv + (size_t)(b * S_ + s) * NQKV + which * D_ + h * HD_;
    float x1 = src[i];
    float x2 = src[i + 32];
    float* dst = (which == 0 ? q : which == 1 ? k : v)
               + (size_t)((b * H_ + h) * S_ + s) * HD_;
    if (which == 2) {
        dst[i]      = x1;
        dst[i + 32] = x2;
    } else {
        float inv = powf(10000.0f, -(float)i * (1.0f / 32.0f));
        float ang = (float)s * inv;
        float sn, c;
        sincosf(ang, &sn, &c);
        dst[i]      = x1 * c - x2 * sn;
        dst[i + 32] = x1 * sn + x2 * c;
    }
}

// ---------------------------------------------------------------------------
// Causal flash attention on tensor cores (3xTF32 mma.sync, near-fp32 accuracy).
// BM=128 (8 warps x 16 rows), BN=64, Hd=64. Q frags in registers,
// K/V/P staged fp32 in smem, hi/lo tf32 split at fragment-load time.
// ---------------------------------------------------------------------------
#define LDK 68
#define LDV 72
#define LDP 68

__global__ __launch_bounds__(256) void flash_attn_tc_kernel(
    const float* __restrict__ Q, const float* __restrict__ K,
    const float* __restrict__ V, float* __restrict__ Oattn)
{
    extern __shared__ float sm[];
    float* sK = sm;                 // [64][LDK]  [keypos][d]
    float* sV = sK + 64 * LDK;      // [64][LDV]  [keypos][d]
    float* sP = sV + 64 * LDV;      // [128][LDP] [qrow_local][keypos]

    const int tid  = threadIdx.x;
    const int lane = tid & 31;
    const int wid  = tid >> 5;
    const int g    = lane >> 2;     // row group 0..7
    const int t    = lane & 3;      // thread-in-group
    const int qt   = (int)gridDim.x - 1 - (int)blockIdx.x;  // big tiles first
    const int bh   = blockIdx.y;

    const float* Qb = Q + (size_t)bh * S_ * HD_;
    const float* Kb = K + (size_t)bh * S_ * HD_;
    const float* Vb = V + (size_t)bh * S_ * HD_;

    const int row0 = qt * 128 + wid * 16 + g;   // global q row (slots 0,1)
    const int rl   = wid * 16 + g;              // local row in sP

    // Q fragments (tf32 hi/lo), loop-invariant in registers
    unsigned qh[8][4], ql[8][4];
#pragma unroll
    for (int kf = 0; kf < 8; kf++) {
#pragma unroll
        for (int ss = 0; ss < 4; ss++) {
            int r = row0 + ((ss & 1) ? 8 : 0);
            int c = kf * 8 + t + ((ss & 2) ? 4 : 0);
            float v  = Qb[(size_t)r * HD_ + c];
            float hi = tf32_rna(v);
            qh[kf][ss] = __float_as_uint(hi);
            ql[kf][ss] = __float_as_uint(v - hi);
        }
    }

    float o[8][4];
#pragma unroll
    for (int nf = 0; nf < 8; nf++)
#pragma unroll
        for (int ss = 0; ss < 4; ss++) o[nf][ss] = 0.f;
    float m0 = -1e30f, m1 = -1e30f, l0 = 0.f, l1 = 0.f;

    const int jend = 2 * qt + 2;
    for (int jt = 0; jt < jend; jt++) {
        __syncthreads();   // previous iteration fully done before restaging
#pragma unroll
        for (int p = 0; p < 4; p++) {
            int slot = p * 256 + tid;
            int r = slot >> 4, c4 = slot & 15;
            *(float4*)&sK[r * LDK + c4 * 4] =
                *(const float4*)(Kb + (size_t)(jt * 64 + r) * HD_ + c4 * 4);
            *(float4*)&sV[r * LDV + c4 * 4] =
                *(const float4*)(Vb + (size_t)(jt * 64 + r) * HD_ + c4 * 4);
        }
        __syncthreads();

        // ---- S = Q K^T (3xTF32) ----
        float s_[8][4];
#pragma unroll
        for (int nf = 0; nf < 8; nf++)
#pragma unroll
            for (int ss = 0; ss < 4; ss++) s_[nf][ss] = 0.f;

#pragma unroll
        for (int nf = 0; nf < 8; nf++) {
#pragma unroll
            for (int kf = 0; kf < 8; kf++) {
                float b0f = sK[(nf * 8 + g) * LDK + kf * 8 + t];
                float b1f = sK[(nf * 8 + g) * LDK + kf * 8 + t + 4];
                float b0h = tf32_rna(b0f), b1h = tf32_rna(b1f);
                unsigned ub0h = __float_as_uint(b0h), ub1h = __float_as_uint(b1h);
                unsigned ub0l = __float_as_uint(b0f - b0h), ub1l = __float_as_uint(b1f - b1h);
                mma8(s_[nf], qh[kf], ub0h, ub1h);
                mma8(s_[nf], qh[kf], ub0l, ub1l);
                mma8(s_[nf], ql[kf], ub0h, ub1h);
            }
        }

        // ---- mask + scale + online softmax (warp-local) ----
        float rmax0 = -1e30f, rmax1 = -1e30f;
#pragma unroll
        for (int nf = 0; nf < 8; nf++) {
#pragma unroll
            for (int par = 0; par < 2; par++) {
                int col = jt * 64 + nf * 8 + 2 * t + par;
                float v0 = s_[nf][par] * 0.125f;
                if (col > row0) v0 = -1e30f;
                s_[nf][par] = v0; rmax0 = fmaxf(rmax0, v0);
                float v1 = s_[nf][2 + par] * 0.125f;
                if (col > row0 + 8) v1 = -1e30f;
                s_[nf][2 + par] = v1; rmax1 = fmaxf(rmax1, v1);
            }
        }
        rmax0 = fmaxf(rmax0, __shfl_xor_sync(0xffffffffu, rmax0, 1));
        rmax0 = fmaxf(rmax0, __shfl_xor_sync(0xffffffffu, rmax0, 2));
        rmax1 = fmaxf(rmax1, __shfl_xor_sync(0xffffffffu, rmax1, 1));
        rmax1 = fmaxf(rmax1, __shfl_xor_sync(0xffffffffu, rmax1, 2));

        float nm0 = fmaxf(m0, rmax0), nm1 = fmaxf(m1, rmax1);
        float c0 = __expf(m0 - nm0), c1 = __expf(m1 - nm1);
        float sum0 = 0.f, sum1 = 0.f;
#pragma unroll
        for (int nf = 0; nf < 8; nf++) {
#pragma unroll
            for (int par = 0; par < 2; par++) {
                float p0 = __expf(s_[nf][par] - nm0);
                s_[nf][par] = p0; sum0 += p0;
                float p1 = __expf(s_[nf][2 + par] - nm1);
                s_[nf][2 + par] = p1; sum1 += p1;
            }
        }
        sum0 += __shfl_xor_sync(0xffffffffu, sum0, 1);
        sum0 += __shfl_xor_sync(0xffffffffu, sum0, 2);
        sum1 += __shfl_xor_sync(0xffffffffu, sum1, 1);
        sum1 += __shfl_xor_sync(0xffffffffu, sum1, 2);
        l0 = l0 * c0 + sum0; l1 = l1 * c1 + sum1;
        m0 = nm0; m1 = nm1;
#pragma unroll
        for (int nf = 0; nf < 8; nf++) {
            o[nf][0] *= c0; o[nf][1] *= c0;
            o[nf][2] *= c1; o[nf][3] *= c1;
        }

        // ---- P -> smem (warp-private region), then O += P V (3xTF32) ----
#pragma unroll
        for (int nf = 0; nf < 8; nf++) {
#pragma unroll
            for (int par = 0; par < 2; par++) {
                sP[rl * LDP + nf * 8 + 2 * t + par]       = s_[nf][par];
                sP[(rl + 8) * LDP + nf * 8 + 2 * t + par] = s_[nf][2 + par];
            }
        }
        __syncwarp();

#pragma unroll
        for (int kf = 0; kf < 8; kf++) {
            float a0f = sP[rl * LDP + kf * 8 + t];
            float a1f = sP[(rl + 8) * LDP + kf * 8 + t];
            float a2f = sP[rl * LDP + kf * 8 + t + 4];
            float a3f = sP[(rl + 8) * LDP + kf * 8 + t + 4];
            float a0h = tf32_rna(a0f), a1h = tf32_rna(a1f);
            float a2h = tf32_rna(a2f), a3h = tf32_rna(a3f);
            unsigned ph[4] = {__float_as_uint(a0h), __float_as_uint(a1h),
                              __float_as_uint(a2h), __float_as_uint(a3h)};
            unsigned pl[4] = {__float_as_uint(a0f - a0h), __float_as_uint(a1f - a1h),
                              __float_as_uint(a2f - a2h), __float_as_uint(a3f - a3h)};
#pragma unroll
            for (int nf = 0; nf < 8; nf++) {
                float b0f = sV[(kf * 8 + t) * LDV + nf * 8 + g];
                float b1f = sV[(kf * 8 + t + 4) * LDV + nf * 8 + g];
                float b0h = tf32_rna(b0f), b1h = tf32_rna(b1f);
                unsigned ub0h = __float_as_uint(b0h), ub1h = __float_as_uint(b1h);
                mma8(o[nf], ph, ub0h, ub1h);
                mma8(o[nf], ph, __float_as_uint(b0f - b0h), __float_as_uint(b1f - b1h));
                mma8(o[nf], pl, ub0h, ub1h);
            }
        }
    }

    // ---- epilogue: normalize + write [B,S,D] at head offset ----
    float il0 = 1.f / l0, il1 = 1.f / l1;
    int b = bh >> 4, h = bh & 15;
#pragma unroll
    for (int nf = 0; nf < 8; nf++) {
        float2 w0 = make_float2(o[nf][0] * il0, o[nf][1] * il0);
        float2 w1 = make_float2(o[nf][2] * il1, o[nf][3] * il1);
        *(float2*)&Oattn[((size_t)b * S_ + row0) * D_ + h * HD_ + nf * 8 + 2 * t] = w0;
        *(float2*)&Oattn[((size_t)b * S_ + row0 + 8) * D_ + h * HD_ + nf * 8 + 2 * t] = w1;
    }
}

// ---------------------------------------------------------------------------
extern "C" void kernel_launch(void* const* d_in, const int* in_sizes, int n_in,
                              void* d_out, int out_size)
{
    const float* x     = (const float*)d_in[0];
    const float* qkv_w = (const float*)d_in[1];
    const float* qkv_b = (const float*)d_in[2];
    const float* out_w = (const float*)d_in[3];
    const float* out_b = (const float*)d_in[4];
    float* out = (float*)d_out;

    float *qkv, *q, *k, *v, *attn;
    cudaGetSymbolAddress((void**)&qkv,  g_qkv);
    cudaGetSymbolAddress((void**)&q,    g_q);
    cudaGetSymbolAddress((void**)&k,    g_k);
    cudaGetSymbolAddress((void**)&v,    g_v);
    cudaGetSymbolAddress((void**)&attn, g_attn);

    // 1) QKV projection: [4096,1024] @ [3072,1024]^T + bias (3xTF32 tensor cores)
    tf32_gemm_bias_kernel<<<dim3(NQKV / 128, M_ / 128), 256>>>(
        x, qkv_w, qkv_b, qkv, M_, NQKV, KD);

    // 2) RoPE + scatter to [B,H,S,Hd]
    {
        const int TOT = 3 * B_ * H_ * S_ * 32;
        rope_scatter_kernel<<<(TOT + 255) / 256, 256>>>(qkv, q, k, v);
    }

    // 3) Causal flash attention (tensor cores, 3xTF32)
    {
        int smem = (64 * LDK + 64 * LDV + 128 * LDP) * sizeof(float);  // 70656 B
        cudaFuncSetAttribute(flash_attn_tc_kernel,
                             cudaFuncAttributeMaxDynamicSharedMemorySize, smem);
        flash_attn_tc_kernel<<<dim3(S_ / 128, B_ * H_), 256, smem>>>(q, k, v, attn);
    }

    // 4) Output projection: [4096,1024] @ [1024,1024]^T + bias (3xTF32 tensor cores)
    tf32_gemm_bias_kernel<<<dim3(D_ / 128, M_ / 128), 256>>>(
        attn, out_w, out_b, out, M_, D_, KD);
}